// round 13
// baseline (speedup 1.0000x reference)
#include <cuda_runtime.h>
#include <cuda_bf16.h>
#include <math.h>

// predictions [16,1,512,512] f32, targets [16,1,512,512] i32, output scalar f32.
#define NIMG 16
#define H 512
#define W 512
#define NPIX (NIMG * H * W)
#define NBLK 2048
#define IINF (1 << 20)
#define HALO 16
#define SROWS 96           // 64 tile rows + 2*HALO

// Float planes written by rowpass:
//  g_f2 = gf^2           (squared 1D dist to nearest FG site)  -- used by BG pixels
//  g_b2 = +/- gb^2       (squared 1D dist to nearest BG site; SIGN BIT = target)
__device__ float g_f2[NIMG * H * W];
__device__ float g_b2[NIMG * H * W];
__device__ double g_part[NBLK][5];
__device__ int g_ticket;

__device__ __forceinline__ float fsqrt_approx(float x) {
    float r;
    asm("sqrt.approx.f32 %0, %1;" : "=f"(r) : "f"(x));
    return r;
}
__device__ __forceinline__ float sigmoid_fast(float x) {
    float e, r;
    asm("ex2.approx.f32 %0, %1;" : "=f"(e) : "f"(-1.4426950408889634f * x));
    asm("rcp.approx.f32 %0, %1;" : "=f"(r) : "f"(1.0f + e));
    return r;
}

// One warp per row; each thread owns 16 CONTIGUOUS pixels.
__global__ void k_rowpass(const int* __restrict__ tg) {
    if (blockIdx.x == 0 && threadIdx.x == 0) g_ticket = 0;
    const int warp = threadIdx.x >> 5, lane = threadIdx.x & 31;
    const int row = blockIdx.x * 4 + warp;           // 8192 rows total
    const unsigned FULL = 0xFFFFFFFFu;

    const int4* tr = (const int4*)(tg + (size_t)row * W) + lane * 4;
    int m = 0;
    {
        int4 a = tr[0], b4 = tr[1], c = tr[2], d = tr[3];
        int v[16] = {a.x, a.y, a.z, a.w, b4.x, b4.y, b4.z, b4.w,
                     c.x, c.y, c.z, c.w, d.x, d.y, d.z, d.w};
#pragma unroll
        for (int j = 0; j < 16; j++) m |= (v[j] != 0) << j;
    }
    const int pbase = lane * 16;

    int laf[16], lab[16];
    int rf = IINF, rb = IINF;
#pragma unroll
    for (int j = 0; j < 16; j++) {
        int p = pbase + j;
        int bit = (m >> j) & 1;
        rf = min(rf, bit ? -p : IINF);
        rb = min(rb, bit ? IINF : -p);
        laf[j] = rf; lab[j] = rb;
    }
    int vf = rf, vb = rb;
#pragma unroll
    for (int o = 1; o < 32; o <<= 1) {
        int nf = __shfl_up_sync(FULL, vf, o);
        int nb = __shfl_up_sync(FULL, vb, o);
        if (lane >= o) { vf = min(vf, nf); vb = min(vb, nb); }
    }
    int ef = __shfl_up_sync(FULL, vf, 1); if (lane == 0) ef = IINF;
    int eb = __shfl_up_sync(FULL, vb, 1); if (lane == 0) eb = IINF;
#pragma unroll
    for (int j = 0; j < 16; j++) {
        int p = pbase + j;
        laf[j] = p + min(laf[j], ef);
        lab[j] = p + min(lab[j], eb);
    }

    int lbf[16], lbb[16];
    rf = IINF; rb = IINF;
#pragma unroll
    for (int j = 15; j >= 0; j--) {
        int p = pbase + j;
        int bit = (m >> j) & 1;
        rf = min(rf, bit ? p : IINF);
        rb = min(rb, bit ? IINF : p);
        lbf[j] = rf; lbb[j] = rb;
    }
    vf = rf; vb = rb;
#pragma unroll
    for (int o = 1; o < 32; o <<= 1) {
        int nf = __shfl_down_sync(FULL, vf, o);
        int nb = __shfl_down_sync(FULL, vb, o);
        if (lane + o < 32) { vf = min(vf, nf); vb = min(vb, nb); }
    }
    ef = __shfl_down_sync(FULL, vf, 1); if (lane == 31) ef = IINF;
    eb = __shfl_down_sync(FULL, vb, 1); if (lane == 31) eb = IINF;

    float* outf = g_f2 + (size_t)row * W + pbase;
    float* outb = g_b2 + (size_t)row * W + pbase;
#pragma unroll
    for (int q = 0; q < 4; q++) {
        float tf[4], tb[4];
#pragma unroll
        for (int jj = 0; jj < 4; jj++) {
            int j = q * 4 + jj;
            int p = pbase + j;
            int Bf = -p + min(lbf[j], ef);
            int Bb = -p + min(lbb[j], eb);
            int gf = min(min(laf[j], Bf), 1024);
            int gb = min(min(lab[j], Bb), 1024);
            float ff = (float)(gf * gf);
            float fb = (float)(gb * gb);
            int bit = (m >> j) & 1;
            tf[jj] = ff;
            tb[jj] = __int_as_float(__float_as_int(fb) | (bit << 31));
        }
        ((float4*)outf)[q] = make_float4(tf[0], tf[1], tf[2], tf[3]);
        ((float4*)outb)[q] = make_float4(tb[0], tb[1], tb[2], tb[3]);
    }
}

// Column envelope from pre-squared float SMEM tiles; per-pixel warp-uniform
// escapes (low live-state, no spills); fused sigmoid + partial sums +
// ticketed grid-final reduction. SMEM kept < 28.5KB for 8 blocks/SM.
__global__ void __launch_bounds__(256, 8)
k_colpass(const float* __restrict__ pred, float* __restrict__ out) {
    __shared__ float sf[SROWS * 32];   // gf^2
    __shared__ float sb[SROWS * 32];   // +/- gb^2 (sign=target)
    __shared__ double shr[5][8];
    __shared__ double shr2[4][8];
    __shared__ double simg[NIMG];
    __shared__ int slast;

    const int tx = threadIdx.x;
    const int ty = threadIdx.y;
    const int xblk = blockIdx.x * 32;
    const int x = xblk + tx;
    const int img = blockIdx.z;
    const int ybase0 = blockIdx.y * 64;
    const size_t ibase = (size_t)img * H * W;
    const unsigned FULL = 0xFFFFFFFFu;

    // ---- tile load: straight float4 copy; 4 rows per warp per iteration ----
    {
        const int seg = tx & 7;
        const int rsub = tx >> 3;
        const float4* pf = (const float4*)(g_f2 + ibase);
        const float4* pb = (const float4*)(g_b2 + ibase);
        const int segbase = (xblk >> 2) + seg;
#pragma unroll
        for (int it = 0; it < 3; it++) {        // 3*32 = 96 rows
            int r = it * 32 + ty * 4 + rsub;
            int gy = ybase0 - HALO + r;
            float4 vf4 = make_float4(1e9f, 1e9f, 1e9f, 1e9f);
            float4 vb4 = vf4;
            if (gy >= 0 && gy < H) {
                vf4 = pf[gy * (W / 4) + segbase];
                vb4 = pb[gy * (W / 4) + segbase];
            }
            ((float4*)sf)[r * 8 + seg] = vf4;
            ((float4*)sb)[r * 8 + seg] = vb4;
        }
    }

    // prefetch predictions (8 rows, stride W)
    float pv[8];
    {
        const float* pp = pred + ibase + (size_t)(ybase0 + ty * 8) * W + x;
#pragma unroll
        for (int k = 0; k < 8; k++) pv[k] = pp[k * W];
    }
    __syncthreads();

    float s0 = 0.f, s1 = 0.f, s2 = 0.f, s3n = 0.f, s3p = 0.f;
    const int cbase = (HALO + ty * 8) * 32 + tx;

#pragma unroll
    for (int k = 0; k < 8; k++) {
        const int ci = cbase + k * 32;
        const float cb = sb[ci];
        const float cf = sf[ci];
        const bool tv = cb < 0.0f;
        float best = tv ? -cb : cf;
        const float* col = (tv ? sb : sf) + ci;

        // chunk 1: dy = 1..4 (unconditional)
        {
            float m1 = fminf(fabsf(col[-1 * 32]), fabsf(col[1 * 32])) + 1.f;
            float m2 = fminf(fabsf(col[-2 * 32]), fabsf(col[2 * 32])) + 4.f;
            float m3 = fminf(fabsf(col[-3 * 32]), fabsf(col[3 * 32])) + 9.f;
            float m4 = fminf(fabsf(col[-4 * 32]), fabsf(col[4 * 32])) + 16.f;
            best = fminf(best, fminf(fminf(m1, m2), fminf(m3, m4)));
        }
        if (__any_sync(FULL, best > 25.f)) {          // dy = 5..16 (within halo)
            float acc = best;
#pragma unroll
            for (int dy = 5; dy <= 16; dy++) {
                float mm = fminf(fabsf(col[-dy * 32]), fabsf(col[dy * 32])) +
                           (float)(dy * dy);
                acc = fminf(acc, mm);
            }
            best = acc;
            if (__any_sync(FULL, best > 289.f)) {     // global fallback (never on real data)
                const int y = ybase0 + ty * 8 + k;
                const float* gcol = (tv ? g_b2 : g_f2) + ibase + x;
                for (int dy = HALO + 1; dy < H; ++dy) {
                    float dy2 = (float)(dy * dy);
                    if (__all_sync(FULL, dy2 >= best)) break;
                    int yu = y - dy, yd = y + dy;
                    if (yu >= 0) best = fminf(best, fabsf(gcol[yu * W]) + dy2);
                    if (yd < H)  best = fminf(best, fabsf(gcol[yd * W]) + dy2);
                }
            }
        }

        float p = sigmoid_fast(pv[k]);
        float phi = fsqrt_approx(best);
        float pp = phi * p;
        s0 += p;
        if (tv) { s1 += p; s2 += 1.f; s3n -= pp; }
        else    { s3p += pp; }
    }

    // warp shuffle reduce, then tiny smem reduce over 8 warps
#pragma unroll
    for (int o = 16; o > 0; o >>= 1) {
        s0 += __shfl_down_sync(FULL, s0, o);
        s1 += __shfl_down_sync(FULL, s1, o);
        s2 += __shfl_down_sync(FULL, s2, o);
        s3n += __shfl_down_sync(FULL, s3n, o);
        s3p += __shfl_down_sync(FULL, s3p, o);
    }
    if (tx == 0) {
        shr[0][ty] = (double)s0; shr[1][ty] = (double)s1; shr[2][ty] = (double)s2;
        shr[3][ty] = (double)s3n; shr[4][ty] = (double)s3p;
    }
    __syncthreads();

    const int tid = ty * 32 + tx;
    const int bid = (blockIdx.z * gridDim.y + blockIdx.y) * gridDim.x + blockIdx.x;
    if (tid == 0) {
#pragma unroll
        for (int q = 0; q < 5; q++) {
            double a = 0;
#pragma unroll
            for (int wgi = 0; wgi < 8; wgi++) a += shr[q][wgi];
            g_part[bid][q] = a;
        }
        __threadfence();
        slast = (atomicAdd(&g_ticket, 1) == NBLK - 1);
    }
    __syncthreads();
    if (!slast) return;
    __threadfence();

    // ---- last block: deterministic final reduction (shuffle-based) ----
    const int wid = tid >> 5, ln = tid & 31;
#pragma unroll
    for (int t = 0; t < 2; t++) {
        int im = wid * 2 + t;
        double s = 0;
        for (int e = ln; e < 128; e += 32) s += g_part[im * 128 + e][2];
#pragma unroll
        for (int o = 16; o > 0; o >>= 1) s += __shfl_down_sync(FULL, s, o);
        if (ln == 0) simg[im] = s;
    }
    __syncthreads();

    double a0 = 0, a1 = 0, a2 = 0, a3 = 0;
    for (int e = tid; e < NBLK; e += 256) {
        int im = e >> 7;
        double st = simg[im];
        bool anyfg = st > 0.0;
        bool anybg = st < (double)(H * W);
        a0 += g_part[e][0]; a1 += g_part[e][1]; a2 += g_part[e][2];
        if (anyfg) a3 += g_part[e][4] + (anybg ? g_part[e][3] : 0.0);
    }
#pragma unroll
    for (int o = 16; o > 0; o >>= 1) {
        a0 += __shfl_down_sync(FULL, a0, o);
        a1 += __shfl_down_sync(FULL, a1, o);
        a2 += __shfl_down_sync(FULL, a2, o);
        a3 += __shfl_down_sync(FULL, a3, o);
    }
    if (ln == 0) {
        shr2[0][wid] = a0; shr2[1][wid] = a1; shr2[2][wid] = a2; shr2[3][wid] = a3;
    }
    __syncthreads();
    if (tid == 0) {
        double sum_p = 0, inter = 0, sum_t = 0, sb_ = 0;
#pragma unroll
        for (int wgi = 0; wgi < 8; wgi++) {
            sum_p += shr2[0][wgi]; inter += shr2[1][wgi];
            sum_t += shr2[2][wgi]; sb_ += shr2[3][wgi];
        }
        double smooth = 1e-06;
        double dice = 1.0 - (2.0 * inter + smooth) / (sum_p + sum_t + smooth);
        double loss = 0.99 * dice + 0.01 * (sb_ / (double)NPIX);
        out[0] = (float)loss;
    }
}

extern "C" void kernel_launch(void* const* d_in, const int* in_sizes, int n_in,
                              void* d_out, int out_size) {
    const float* pred = (const float*)d_in[0];
    const int*   targ = (const int*)d_in[1];
    float* out = (float*)d_out;

    k_rowpass<<<2048, 128>>>(targ);
    dim3 cb(32, 8, 1);
    dim3 cg(W / 32, H / 64, NIMG);   // 2048 blocks
    k_colpass<<<cg, cb>>>(pred, out);
}

// round 14
// speedup vs baseline: 1.4685x; 1.4685x over previous
#include <cuda_runtime.h>
#include <cuda_bf16.h>
#include <math.h>

// predictions [16,1,512,512] f32, targets [16,1,512,512] i32, output scalar f32.
#define NIMG 16
#define H 512
#define W 512
#define NPIX (NIMG * H * W)
#define NBLK 2048
#define IINF (1 << 20)
#define HALO 8
#define SROWS 80           // 64 tile rows + 2*HALO

// Float planes written by rowpass:
//  g_f2 = gf^2           (squared 1D dist to nearest FG site)  -- used by BG pixels
//  g_b2 = +/- gb^2       (squared 1D dist to nearest BG site; SIGN BIT = target)
__device__ float g_f2[NIMG * H * W];
__device__ float g_b2[NIMG * H * W];
__device__ double g_part[NBLK][5];
__device__ int g_ticket;

__device__ __forceinline__ float fsqrt_approx(float x) {
    float r;
    asm("sqrt.approx.f32 %0, %1;" : "=f"(r) : "f"(x));
    return r;
}
__device__ __forceinline__ float sigmoid_fast(float x) {
    float e, r;
    asm("ex2.approx.f32 %0, %1;" : "=f"(e) : "f"(-1.4426950408889634f * x));
    asm("rcp.approx.f32 %0, %1;" : "=f"(r) : "f"(1.0f + e));
    return r;
}

// One warp per row; each thread owns 16 CONTIGUOUS pixels.
__global__ void k_rowpass(const int* __restrict__ tg) {
    if (blockIdx.x == 0 && threadIdx.x == 0) g_ticket = 0;
    const int warp = threadIdx.x >> 5, lane = threadIdx.x & 31;
    const int row = blockIdx.x * 4 + warp;           // 8192 rows total
    const unsigned FULL = 0xFFFFFFFFu;

    const int4* tr = (const int4*)(tg + (size_t)row * W) + lane * 4;
    int m = 0;
    {
        int4 a = tr[0], b4 = tr[1], c = tr[2], d = tr[3];
        int v[16] = {a.x, a.y, a.z, a.w, b4.x, b4.y, b4.z, b4.w,
                     c.x, c.y, c.z, c.w, d.x, d.y, d.z, d.w};
#pragma unroll
        for (int j = 0; j < 16; j++) m |= (v[j] != 0) << j;
    }
    const int pbase = lane * 16;

    int laf[16], lab[16];
    int rf = IINF, rb = IINF;
#pragma unroll
    for (int j = 0; j < 16; j++) {
        int p = pbase + j;
        int bit = (m >> j) & 1;
        rf = min(rf, bit ? -p : IINF);
        rb = min(rb, bit ? IINF : -p);
        laf[j] = rf; lab[j] = rb;
    }
    int vf = rf, vb = rb;
#pragma unroll
    for (int o = 1; o < 32; o <<= 1) {
        int nf = __shfl_up_sync(FULL, vf, o);
        int nb = __shfl_up_sync(FULL, vb, o);
        if (lane >= o) { vf = min(vf, nf); vb = min(vb, nb); }
    }
    int ef = __shfl_up_sync(FULL, vf, 1); if (lane == 0) ef = IINF;
    int eb = __shfl_up_sync(FULL, vb, 1); if (lane == 0) eb = IINF;
#pragma unroll
    for (int j = 0; j < 16; j++) {
        int p = pbase + j;
        laf[j] = p + min(laf[j], ef);
        lab[j] = p + min(lab[j], eb);
    }

    int lbf[16], lbb[16];
    rf = IINF; rb = IINF;
#pragma unroll
    for (int j = 15; j >= 0; j--) {
        int p = pbase + j;
        int bit = (m >> j) & 1;
        rf = min(rf, bit ? p : IINF);
        rb = min(rb, bit ? IINF : p);
        lbf[j] = rf; lbb[j] = rb;
    }
    vf = rf; vb = rb;
#pragma unroll
    for (int o = 1; o < 32; o <<= 1) {
        int nf = __shfl_down_sync(FULL, vf, o);
        int nb = __shfl_down_sync(FULL, vb, o);
        if (lane + o < 32) { vf = min(vf, nf); vb = min(vb, nb); }
    }
    ef = __shfl_down_sync(FULL, vf, 1); if (lane == 31) ef = IINF;
    eb = __shfl_down_sync(FULL, vb, 1); if (lane == 31) eb = IINF;

    float* outf = g_f2 + (size_t)row * W + pbase;
    float* outb = g_b2 + (size_t)row * W + pbase;
#pragma unroll
    for (int q = 0; q < 4; q++) {
        float tf[4], tb[4];
#pragma unroll
        for (int jj = 0; jj < 4; jj++) {
            int j = q * 4 + jj;
            int p = pbase + j;
            int Bf = -p + min(lbf[j], ef);
            int Bb = -p + min(lbb[j], eb);
            int gf = min(min(laf[j], Bf), 1024);
            int gb = min(min(lab[j], Bb), 1024);
            float ff = (float)(gf * gf);
            float fb = (float)(gb * gb);
            int bit = (m >> j) & 1;
            tf[jj] = ff;
            tb[jj] = __int_as_float(__float_as_int(fb) | (bit << 31));
        }
        ((float4*)outf)[q] = make_float4(tf[0], tf[1], tf[2], tf[3]);
        ((float4*)outb)[q] = make_float4(tb[0], tb[1], tb[2], tb[3]);
    }
}

// Column envelope from pre-squared float SMEM tiles; warp-uniform escapes;
// fused sigmoid + partial sums + ticketed grid-final reduction.
__global__ void __launch_bounds__(256, 8)
k_colpass(const float* __restrict__ pred, float* __restrict__ out) {
    __shared__ float sf[SROWS * 32];   // gf^2
    __shared__ float sb[SROWS * 32];   // +/- gb^2 (sign=target)
    __shared__ double shr[5][8];

    const int tx = threadIdx.x;
    const int ty = threadIdx.y;
    const int xblk = blockIdx.x * 32;
    const int x = xblk + tx;
    const int img = blockIdx.z;
    const int ybase0 = blockIdx.y * 64;
    const size_t ibase = (size_t)img * H * W;
    const unsigned FULL = 0xFFFFFFFFu;

    // ---- tile load: straight float4 copy over 80 rows (flat index) ----
    {
        const int tid0 = ty * 32 + tx;
        const float4* pf = (const float4*)(g_f2 + ibase);
        const float4* pb = (const float4*)(g_b2 + ibase);
        for (int i = tid0; i < SROWS * 8; i += 256) {
            int r = i >> 3;
            int seg = i & 7;
            int gy = ybase0 - HALO + r;
            float4 vf4 = make_float4(1e9f, 1e9f, 1e9f, 1e9f);
            float4 vb4 = vf4;
            if (gy >= 0 && gy < H) {
                int gi = gy * (W / 4) + (xblk >> 2) + seg;
                vf4 = pf[gi];
                vb4 = pb[gi];
            }
            ((float4*)sf)[r * 8 + seg] = vf4;
            ((float4*)sb)[r * 8 + seg] = vb4;
        }
    }

    // prefetch predictions (8 rows, stride W)
    float pv[8];
    {
        const float* pp = pred + ibase + (size_t)(ybase0 + ty * 8) * W + x;
#pragma unroll
        for (int k = 0; k < 8; k++) pv[k] = pp[k * W];
    }
    __syncthreads();

    float s0 = 0.f, s1 = 0.f, s2 = 0.f, s3n = 0.f, s3p = 0.f;
    const int cbase = (HALO + ty * 8) * 32 + tx;

#pragma unroll
    for (int k = 0; k < 8; k++) {
        const int ci = cbase + k * 32;
        const float cb = sb[ci];
        const float cf = sf[ci];
        const bool tv = cb < 0.0f;
        float best = tv ? -cb : cf;
        const float* col = (tv ? sb : sf) + ci;

        // chunk 1: dy = 1..4 (unconditional)
        {
            float m1 = fminf(fabsf(col[-1 * 32]), fabsf(col[1 * 32])) + 1.f;
            float m2 = fminf(fabsf(col[-2 * 32]), fabsf(col[2 * 32])) + 4.f;
            float m3 = fminf(fabsf(col[-3 * 32]), fabsf(col[3 * 32])) + 9.f;
            float m4 = fminf(fabsf(col[-4 * 32]), fabsf(col[4 * 32])) + 16.f;
            best = fminf(best, fminf(fminf(m1, m2), fminf(m3, m4)));
        }
        if (__any_sync(FULL, best > 25.f)) {          // dy = 5..8 (within halo)
            float acc = best;
#pragma unroll
            for (int dy = 5; dy <= 8; dy++) {
                float mm = fminf(fabsf(col[-dy * 32]), fabsf(col[dy * 32])) +
                           (float)(dy * dy);
                acc = fminf(acc, mm);
            }
            best = acc;
            if (__any_sync(FULL, best > 81.f)) {      // global fallback (never on real data)
                const int y = ybase0 + ty * 8 + k;
                const float* gcol = (tv ? g_b2 : g_f2) + ibase + x;
                for (int dy = HALO + 1; dy < H; ++dy) {
                    float dy2 = (float)(dy * dy);
                    if (__all_sync(FULL, dy2 >= best)) break;
                    int yu = y - dy, yd = y + dy;
                    if (yu >= 0) best = fminf(best, fabsf(gcol[yu * W]) + dy2);
                    if (yd < H)  best = fminf(best, fabsf(gcol[yd * W]) + dy2);
                }
            }
        }

        float p = sigmoid_fast(pv[k]);
        float phi = fsqrt_approx(best);
        float pp = phi * p;
        s0 += p;
        if (tv) { s1 += p; s2 += 1.f; s3n -= pp; }
        else    { s3p += pp; }
    }

    // warp shuffle reduce, then tiny smem reduce over 8 warps
#pragma unroll
    for (int o = 16; o > 0; o >>= 1) {
        s0 += __shfl_down_sync(FULL, s0, o);
        s1 += __shfl_down_sync(FULL, s1, o);
        s2 += __shfl_down_sync(FULL, s2, o);
        s3n += __shfl_down_sync(FULL, s3n, o);
        s3p += __shfl_down_sync(FULL, s3p, o);
    }
    if (tx == 0) {
        shr[0][ty] = (double)s0; shr[1][ty] = (double)s1; shr[2][ty] = (double)s2;
        shr[3][ty] = (double)s3n; shr[4][ty] = (double)s3p;
    }
    __syncthreads();

    const int tid = ty * 32 + tx;
    const int bid = (blockIdx.z * gridDim.y + blockIdx.y) * gridDim.x + blockIdx.x;
    __shared__ int slast;
    if (tid == 0) {
#pragma unroll
        for (int q = 0; q < 5; q++) {
            double a = 0;
#pragma unroll
            for (int wgi = 0; wgi < 8; wgi++) a += shr[q][wgi];
            g_part[bid][q] = a;
        }
        __threadfence();
        slast = (atomicAdd(&g_ticket, 1) == NBLK - 1);
    }
    __syncthreads();
    if (!slast) return;
    __threadfence();

    // ---- last block: deterministic final reduction ----
    __shared__ double simg[NIMG];
    __shared__ double shfin[4][256];
    const int wid = tid >> 5, ln = tid & 31;
#pragma unroll
    for (int t = 0; t < 2; t++) {
        int im = wid * 2 + t;
        double s = 0;
        for (int e = ln; e < 128; e += 32) s += g_part[im * 128 + e][2];
#pragma unroll
        for (int o = 16; o > 0; o >>= 1) s += __shfl_down_sync(FULL, s, o);
        if (ln == 0) simg[im] = s;
    }
    __syncthreads();

    double a0 = 0, a1 = 0, a2 = 0, a3 = 0;
    for (int e = tid; e < NBLK; e += 256) {
        int im = e >> 7;
        double st = simg[im];
        bool anyfg = st > 0.0;
        bool anybg = st < (double)(H * W);
        a0 += g_part[e][0]; a1 += g_part[e][1]; a2 += g_part[e][2];
        if (anyfg) a3 += g_part[e][4] + (anybg ? g_part[e][3] : 0.0);
    }
    shfin[0][tid] = a0; shfin[1][tid] = a1; shfin[2][tid] = a2; shfin[3][tid] = a3;
    __syncthreads();
    for (int o = 128; o > 0; o >>= 1) {
        if (tid < o) {
#pragma unroll
            for (int q = 0; q < 4; q++) shfin[q][tid] += shfin[q][tid + o];
        }
        __syncthreads();
    }
    if (tid == 0) {
        double sum_p = shfin[0][0], inter = shfin[1][0], sum_t = shfin[2][0], sb_ = shfin[3][0];
        double smooth = 1e-06;
        double dice = 1.0 - (2.0 * inter + smooth) / (sum_p + sum_t + smooth);
        double loss = 0.99 * dice + 0.01 * (sb_ / (double)NPIX);
        out[0] = (float)loss;
    }
}

extern "C" void kernel_launch(void* const* d_in, const int* in_sizes, int n_in,
                              void* d_out, int out_size) {
    const float* pred = (const float*)d_in[0];
    const int*   targ = (const int*)d_in[1];
    float* out = (float*)d_out;

    k_rowpass<<<2048, 128>>>(targ);
    dim3 cb(32, 8, 1);
    dim3 cg(W / 32, H / 64, NIMG);   // 2048 blocks
    k_colpass<<<cg, cb>>>(pred, out);
}

// round 15
// speedup vs baseline: 1.6122x; 1.0979x over previous
#include <cuda_runtime.h>
#include <cuda_bf16.h>
#include <math.h>

// predictions [16,1,512,512] f32, targets [16,1,512,512] i32, output scalar f32.
#define NIMG 16
#define H 512
#define W 512
#define NPIX (NIMG * H * W)
#define NBLK 2048
#define IINF (1 << 20)
#define HALO 8
#define SROWS 80           // 64 tile rows + 2*HALO

// bf16-packed planes (2 px per u32 word; bf16 = top 16 bits of f32):
//  g_f2h: gf^2  (squared 1D dist to nearest FG site)
//  g_b2h: +/- gb^2 (squared 1D dist to nearest BG site; SIGN BIT = target)
__device__ unsigned g_f2h[NIMG * H * W / 2];
__device__ unsigned g_b2h[NIMG * H * W / 2];
__device__ double g_part[NBLK][5];
__device__ int g_ticket;

__device__ __forceinline__ float fsqrt_approx(float x) {
    float r;
    asm("sqrt.approx.f32 %0, %1;" : "=f"(r) : "f"(x));
    return r;
}
__device__ __forceinline__ float sigmoid_fast(float x) {
    float e, r;
    asm("ex2.approx.f32 %0, %1;" : "=f"(e) : "f"(-1.4426950408889634f * x));
    asm("rcp.approx.f32 %0, %1;" : "=f"(r) : "f"(1.0f + e));
    return r;
}

// One warp per row; each thread owns 16 CONTIGUOUS pixels.
__global__ void k_rowpass(const int* __restrict__ tg) {
    if (blockIdx.x == 0 && threadIdx.x == 0) g_ticket = 0;
    const int warp = threadIdx.x >> 5, lane = threadIdx.x & 31;
    const int row = blockIdx.x * 4 + warp;           // 8192 rows total
    const unsigned FULL = 0xFFFFFFFFu;

    const int4* tr = (const int4*)(tg + (size_t)row * W) + lane * 4;
    int m = 0;
    {
        int4 a = tr[0], b4 = tr[1], c = tr[2], d = tr[3];
        int v[16] = {a.x, a.y, a.z, a.w, b4.x, b4.y, b4.z, b4.w,
                     c.x, c.y, c.z, c.w, d.x, d.y, d.z, d.w};
#pragma unroll
        for (int j = 0; j < 16; j++) m |= (v[j] != 0) << j;
    }
    const int pbase = lane * 16;

    int laf[16], lab[16];
    int rf = IINF, rb = IINF;
#pragma unroll
    for (int j = 0; j < 16; j++) {
        int p = pbase + j;
        int bit = (m >> j) & 1;
        rf = min(rf, bit ? -p : IINF);
        rb = min(rb, bit ? IINF : -p);
        laf[j] = rf; lab[j] = rb;
    }
    int vf = rf, vb = rb;
#pragma unroll
    for (int o = 1; o < 32; o <<= 1) {
        int nf = __shfl_up_sync(FULL, vf, o);
        int nb = __shfl_up_sync(FULL, vb, o);
        if (lane >= o) { vf = min(vf, nf); vb = min(vb, nb); }
    }
    int ef = __shfl_up_sync(FULL, vf, 1); if (lane == 0) ef = IINF;
    int eb = __shfl_up_sync(FULL, vb, 1); if (lane == 0) eb = IINF;
#pragma unroll
    for (int j = 0; j < 16; j++) {
        int p = pbase + j;
        laf[j] = p + min(laf[j], ef);
        lab[j] = p + min(lab[j], eb);
    }

    int lbf[16], lbb[16];
    rf = IINF; rb = IINF;
#pragma unroll
    for (int j = 15; j >= 0; j--) {
        int p = pbase + j;
        int bit = (m >> j) & 1;
        rf = min(rf, bit ? p : IINF);
        rb = min(rb, bit ? IINF : p);
        lbf[j] = rf; lbb[j] = rb;
    }
    vf = rf; vb = rb;
#pragma unroll
    for (int o = 1; o < 32; o <<= 1) {
        int nf = __shfl_down_sync(FULL, vf, o);
        int nb = __shfl_down_sync(FULL, vb, o);
        if (lane + o < 32) { vf = min(vf, nf); vb = min(vb, nb); }
    }
    ef = __shfl_down_sync(FULL, vf, 1); if (lane == 31) ef = IINF;
    eb = __shfl_down_sync(FULL, vb, 1); if (lane == 31) eb = IINF;

    // pack two bf16 per word via PRMT (truncation); 8 words per plane per thread
    unsigned wfp[8], wbp[8];
#pragma unroll
    for (int h = 0; h < 8; h++) {
        int j0 = 2 * h, j1 = 2 * h + 1;
        int p0 = pbase + j0, p1 = pbase + j1;
        int Bf0 = -p0 + min(lbf[j0], ef), Bb0 = -p0 + min(lbb[j0], eb);
        int Bf1 = -p1 + min(lbf[j1], ef), Bb1 = -p1 + min(lbb[j1], eb);
        int gf0 = min(min(laf[j0], Bf0), 1024), gb0 = min(min(lab[j0], Bb0), 1024);
        int gf1 = min(min(laf[j1], Bf1), 1024), gb1 = min(min(lab[j1], Bb1), 1024);
        int f0 = __float_as_int((float)(gf0 * gf0));
        int f1 = __float_as_int((float)(gf1 * gf1));
        int b0 = __float_as_int((float)(gb0 * gb0)) | (((m >> j0) & 1) << 31);
        int b1 = __float_as_int((float)(gb1 * gb1)) | (((m >> j1) & 1) << 31);
        wfp[h] = __byte_perm((unsigned)f0, (unsigned)f1, 0x7632);
        wbp[h] = __byte_perm((unsigned)b0, (unsigned)b1, 0x7632);
    }
    unsigned* outf = g_f2h + (size_t)row * (W / 2) + lane * 8;
    unsigned* outb = g_b2h + (size_t)row * (W / 2) + lane * 8;
    ((uint4*)outf)[0] = make_uint4(wfp[0], wfp[1], wfp[2], wfp[3]);
    ((uint4*)outf)[1] = make_uint4(wfp[4], wfp[5], wfp[6], wfp[7]);
    ((uint4*)outb)[0] = make_uint4(wbp[0], wbp[1], wbp[2], wbp[3]);
    ((uint4*)outb)[1] = make_uint4(wbp[4], wbp[5], wbp[6], wbp[7]);
}

// Column envelope from pre-squared float SMEM tiles (unpacked from bf16 at
// load); warp-uniform escapes; fused sigmoid + partial sums + ticketed
// grid-final reduction.
__global__ void __launch_bounds__(256, 8)
k_colpass(const float* __restrict__ pred, float* __restrict__ out) {
    __shared__ float sf[SROWS * 32];   // gf^2
    __shared__ float sb[SROWS * 32];   // +/- gb^2 (sign=target)
    __shared__ double shr[5][8];

    const int tx = threadIdx.x;
    const int ty = threadIdx.y;
    const int xblk = blockIdx.x * 32;
    const int x = xblk + tx;
    const int img = blockIdx.z;
    const int ybase0 = blockIdx.y * 64;
    const size_t ibase = (size_t)img * H * W;
    const size_t ibase2 = (size_t)img * (H * W / 2);
    const unsigned FULL = 0xFFFFFFFFu;

    // ---- tile load: uint4 of bf16-pairs -> f32 smem via shift/mask ----
    {
        const int tid0 = ty * 32 + tx;
        const uint4* pfh = (const uint4*)(g_f2h + ibase2);
        const uint4* pbh = (const uint4*)(g_b2h + ibase2);
        const int rowq = W / 8;                 // uint4 words per row = 64
        // 640 slots: 80 rows x 4 segments x 2 planes (plane = slot&1)
        for (int i = tid0; i < SROWS * 8; i += 256) {
            int pl = i & 1;
            int j = i >> 1;
            int r = j >> 2;
            int seg = j & 3;                    // 8 px per segment
            int gy = ybase0 - HALO + r;
            uint4 u = make_uint4(0x4E6E4E6Eu, 0x4E6E4E6Eu, 0x4E6E4E6Eu, 0x4E6E4E6Eu);
            if (gy >= 0 && gy < H)
                u = (pl ? pbh : pfh)[gy * rowq + (xblk >> 3) + seg];
            float* dst = (pl ? sb : sf) + r * 32 + seg * 8;
            ((float4*)dst)[0] = make_float4(
                __int_as_float((int)(u.x << 16)), __int_as_float((int)(u.x & 0xFFFF0000u)),
                __int_as_float((int)(u.y << 16)), __int_as_float((int)(u.y & 0xFFFF0000u)));
            ((float4*)dst)[1] = make_float4(
                __int_as_float((int)(u.z << 16)), __int_as_float((int)(u.z & 0xFFFF0000u)),
                __int_as_float((int)(u.w << 16)), __int_as_float((int)(u.w & 0xFFFF0000u)));
        }
    }

    // prefetch predictions (8 rows, stride W)
    float pv[8];
    {
        const float* pp = pred + ibase + (size_t)(ybase0 + ty * 8) * W + x;
#pragma unroll
        for (int k = 0; k < 8; k++) pv[k] = pp[k * W];
    }
    __syncthreads();

    float s0 = 0.f, s1 = 0.f, s2 = 0.f, s3n = 0.f, s3p = 0.f;
    const int cbase = (HALO + ty * 8) * 32 + tx;

#pragma unroll
    for (int k = 0; k < 8; k++) {
        const int ci = cbase + k * 32;
        const float cb = sb[ci];
        const float cf = sf[ci];
        const bool tv = cb < 0.0f;
        float best = tv ? -cb : cf;
        const float* col = (tv ? sb : sf) + ci;

        // chunk 1: dy = 1..4 (unconditional)
        {
            float m1 = fminf(fabsf(col[-1 * 32]), fabsf(col[1 * 32])) + 1.f;
            float m2 = fminf(fabsf(col[-2 * 32]), fabsf(col[2 * 32])) + 4.f;
            float m3 = fminf(fabsf(col[-3 * 32]), fabsf(col[3 * 32])) + 9.f;
            float m4 = fminf(fabsf(col[-4 * 32]), fabsf(col[4 * 32])) + 16.f;
            best = fminf(best, fminf(fminf(m1, m2), fminf(m3, m4)));
        }
        if (__any_sync(FULL, best > 25.f)) {          // dy = 5..8 (within halo)
            float acc = best;
#pragma unroll
            for (int dy = 5; dy <= 8; dy++) {
                float mm = fminf(fabsf(col[-dy * 32]), fabsf(col[dy * 32])) +
                           (float)(dy * dy);
                acc = fminf(acc, mm);
            }
            best = acc;
            if (__any_sync(FULL, best > 81.f)) {      // global fallback (never on real data)
                const int y = ybase0 + ty * 8 + k;
                const unsigned* gph = (tv ? g_b2h : g_f2h) + ibase2 + (x >> 1);
                const int odd = x & 1;
                for (int dy = HALO + 1; dy < H; ++dy) {
                    float dy2 = (float)(dy * dy);
                    if (__all_sync(FULL, dy2 >= best)) break;
                    int yu = y - dy, yd = y + dy;
                    if (yu >= 0) {
                        unsigned wv = gph[yu * (W / 2)];
                        float v = __int_as_float(odd ? (int)(wv & 0xFFFF0000u)
                                                     : (int)(wv << 16));
                        best = fminf(best, fabsf(v) + dy2);
                    }
                    if (yd < H) {
                        unsigned wv = gph[yd * (W / 2)];
                        float v = __int_as_float(odd ? (int)(wv & 0xFFFF0000u)
                                                     : (int)(wv << 16));
                        best = fminf(best, fabsf(v) + dy2);
                    }
                }
            }
        }

        float p = sigmoid_fast(pv[k]);
        float phi = fsqrt_approx(best);
        float pp = phi * p;
        s0 += p;
        if (tv) { s1 += p; s2 += 1.f; s3n -= pp; }
        else    { s3p += pp; }
    }

    // warp shuffle reduce, then tiny smem reduce over 8 warps
#pragma unroll
    for (int o = 16; o > 0; o >>= 1) {
        s0 += __shfl_down_sync(FULL, s0, o);
        s1 += __shfl_down_sync(FULL, s1, o);
        s2 += __shfl_down_sync(FULL, s2, o);
        s3n += __shfl_down_sync(FULL, s3n, o);
        s3p += __shfl_down_sync(FULL, s3p, o);
    }
    if (tx == 0) {
        shr[0][ty] = (double)s0; shr[1][ty] = (double)s1; shr[2][ty] = (double)s2;
        shr[3][ty] = (double)s3n; shr[4][ty] = (double)s3p;
    }
    __syncthreads();

    const int tid = ty * 32 + tx;
    const int bid = (blockIdx.z * gridDim.y + blockIdx.y) * gridDim.x + blockIdx.x;
    __shared__ int slast;
    if (tid == 0) {
#pragma unroll
        for (int q = 0; q < 5; q++) {
            double a = 0;
#pragma unroll
            for (int wgi = 0; wgi < 8; wgi++) a += shr[q][wgi];
            g_part[bid][q] = a;
        }
        __threadfence();
        slast = (atomicAdd(&g_ticket, 1) == NBLK - 1);
    }
    __syncthreads();
    if (!slast) return;
    __threadfence();

    // ---- last block: deterministic final reduction ----
    __shared__ double simg[NIMG];
    __shared__ double shfin[4][256];
    const int wid = tid >> 5, ln = tid & 31;
#pragma unroll
    for (int t = 0; t < 2; t++) {
        int im = wid * 2 + t;
        double s = 0;
        for (int e = ln; e < 128; e += 32) s += g_part[im * 128 + e][2];
#pragma unroll
        for (int o = 16; o > 0; o >>= 1) s += __shfl_down_sync(FULL, s, o);
        if (ln == 0) simg[im] = s;
    }
    __syncthreads();

    double a0 = 0, a1 = 0, a2 = 0, a3 = 0;
    for (int e = tid; e < NBLK; e += 256) {
        int im = e >> 7;
        double st = simg[im];
        bool anyfg = st > 0.0;
        bool anybg = st < (double)(H * W);
        a0 += g_part[e][0]; a1 += g_part[e][1]; a2 += g_part[e][2];
        if (anyfg) a3 += g_part[e][4] + (anybg ? g_part[e][3] : 0.0);
    }
    shfin[0][tid] = a0; shfin[1][tid] = a1; shfin[2][tid] = a2; shfin[3][tid] = a3;
    __syncthreads();
    for (int o = 128; o > 0; o >>= 1) {
        if (tid < o) {
#pragma unroll
            for (int q = 0; q < 4; q++) shfin[q][tid] += shfin[q][tid + o];
        }
        __syncthreads();
    }
    if (tid == 0) {
        double sum_p = shfin[0][0], inter = shfin[1][0], sum_t = shfin[2][0], sb_ = shfin[3][0];
        double smooth = 1e-06;
        double dice = 1.0 - (2.0 * inter + smooth) / (sum_p + sum_t + smooth);
        double loss = 0.99 * dice + 0.01 * (sb_ / (double)NPIX);
        out[0] = (float)loss;
    }
}

extern "C" void kernel_launch(void* const* d_in, const int* in_sizes, int n_in,
                              void* d_out, int out_size) {
    const float* pred = (const float*)d_in[0];
    const int*   targ = (const int*)d_in[1];
    float* out = (float*)d_out;

    k_rowpass<<<2048, 128>>>(targ);
    dim3 cb(32, 8, 1);
    dim3 cg(W / 32, H / 64, NIMG);   // 2048 blocks
    k_colpass<<<cg, cb>>>(pred, out);
}